// round 7
// baseline (speedup 1.0000x reference)
#include <cuda_runtime.h>
#include <cuda_bf16.h>

// Problem constants (WordSmoothCriterion: B=4, T=2048, V=32000, NNZ=801)
#define NROWS 8192
#define VDIM  32000
#define NNZ   801
#define TAU   0.8f
#define RARE  1.0f
#define ALPHA 0.7f

#define TPB 128   // threads per CTA
#define EPT 7     // elements per thread (128*7 = 896 >= 801)

// Scratch (device globals — allocation-free)
__device__ float g_smooth[NROWS];   // per-row sum(g*sim)
__device__ float g_ml[NROWS];       // per-row lp[target]*mask
__device__ float g_maskv[NROWS];    // per-row mask
__device__ unsigned int g_count = 0;  // completion counter (self-resetting)

// ---------------------------------------------------------------------------
// Fused kernel: per-row partials + last-block final reduction.
// One CTA per row, 128 threads, 7 front-batched gathers per thread.
// ---------------------------------------------------------------------------
__global__ __launch_bounds__(TPB, 10)
void ws_fused_kernel(const float* __restrict__ logp,
                     const float* __restrict__ mask,
                     const float* __restrict__ sim_values,
                     const float* __restrict__ idf_values,
                     const int*   __restrict__ target,
                     const int*   __restrict__ sim_cols,
                     float*       __restrict__ out)
{
    const int n   = blockIdx.x;
    const int tid = threadIdx.x;
    const int r   = target[n];

    const float* __restrict__ sv = sim_values + (size_t)r * NNZ;
    const float* __restrict__ iv = idf_values + (size_t)r * NNZ;
    const int*   __restrict__ sc = sim_cols   + (size_t)r * NNZ;
    const float* __restrict__ lp = logp       + (size_t)n * VDIM;

    // Hoist the tail loads: in flight during the whole gather phase.
    float m_early = 0.0f, lpr_early = 0.0f;
    if (tid == 0) { m_early = mask[n]; lpr_early = lp[r]; }

    const float inv_tau = 1.0f / TAU;

    // Only the last slice (k = EPT-1: j = 768 + tid) can exceed 801.
    const bool pl = (768 + tid < NNZ);

    // ---- front-batched index loads (coalesced) ----
    int c[EPT];
    #pragma unroll
    for (int k = 0; k < EPT - 1; k++) c[k] = sc[tid + k * TPB];
    c[EPT - 1] = pl ? sc[tid + (EPT - 1) * TPB] : 0;

    // ---- 7 independent scattered gathers in flight ----
    float g[EPT];
    #pragma unroll
    for (int k = 0; k < EPT; k++) g[k] = lp[c[k]];

    // ---- contiguous value streams (coalesced, overlap with gathers) ----
    float s[EPT], d[EPT];
    #pragma unroll
    for (int k = 0; k < EPT - 1; k++) { s[k] = sv[tid + k * TPB]; d[k] = iv[tid + k * TPB]; }
    s[EPT - 1] = pl ? sv[tid + (EPT - 1) * TPB] : 0.0f;
    d[EPT - 1] = pl ? iv[tid + (EPT - 1) * TPB] : 1e9f;   // -> val ~ exp(exp(-big)) but masked below

    // ---- math ----
    float sum_v = 0.0f, sum_gv = 0.0f;
    #pragma unroll
    for (int k = 0; k < EPT; k++) {
        float val = __expf(__expf((s[k] - 1.0f - TAU * RARE * d[k]) * inv_tau) * inv_tau);
        if (k == EPT - 1 && !pl) val = 0.0f;
        sum_v  += val;
        sum_gv += val * g[k];
    }

    // -------- block reduction of (sum_v, sum_gv) --------
    #pragma unroll
    for (int o = 16; o > 0; o >>= 1) {
        sum_v  += __shfl_down_sync(0xffffffffu, sum_v,  o);
        sum_gv += __shfl_down_sync(0xffffffffu, sum_gv, o);
    }
    __shared__ float s_v[4], s_gv[4];
    __shared__ bool  s_last;
    const int warp = tid >> 5;
    const int lane = tid & 31;
    if (lane == 0) { s_v[warp] = sum_v; s_gv[warp] = sum_gv; }
    __syncthreads();
    if (warp == 0) {
        float a = (lane < 4) ? s_v[lane]  : 0.0f;
        float b = (lane < 4) ? s_gv[lane] : 0.0f;
        #pragma unroll
        for (int o = 2; o > 0; o >>= 1) {
            a += __shfl_down_sync(0xffffffffu, a, o);
            b += __shfl_down_sync(0xffffffffu, b, o);
        }
        if (lane == 0) {
            g_smooth[n] = b / a;                        // sum(g * sim) for row n
            g_ml[n]     = lpr_early * m_early;          // lp[n, target[n]] * m[n]
            g_maskv[n]  = m_early;
            __threadfence();                            // make partials visible
            unsigned int old = atomicAdd(&g_count, 1u);
            s_last = (old == (unsigned int)(gridDim.x - 1));
        }
    }
    __syncthreads();

    // -------- last CTA performs the final (deterministic) reduction --------
    if (s_last) {
        double d_sm = 0.0, d_ml = 0.0, d_m = 0.0;
        for (int i = tid; i < NROWS; i += TPB) {
            d_sm += (double)g_smooth[i];
            d_ml += (double)g_ml[i];
            d_m  += (double)g_maskv[i];
        }
        #pragma unroll
        for (int o = 16; o > 0; o >>= 1) {
            d_sm += __shfl_down_sync(0xffffffffu, d_sm, o);
            d_ml += __shfl_down_sync(0xffffffffu, d_ml, o);
            d_m  += __shfl_down_sync(0xffffffffu, d_m,  o);
        }
        __shared__ double sh[3][4];
        if (lane == 0) { sh[0][warp] = d_sm; sh[1][warp] = d_ml; sh[2][warp] = d_m; }
        __syncthreads();
        if (warp == 0) {
            d_sm = (lane < 4) ? sh[0][lane] : 0.0;
            d_ml = (lane < 4) ? sh[1][lane] : 0.0;
            d_m  = (lane < 4) ? sh[2][lane] : 0.0;
            #pragma unroll
            for (int o = 2; o > 0; o >>= 1) {
                d_sm += __shfl_down_sync(0xffffffffu, d_sm, o);
                d_ml += __shfl_down_sync(0xffffffffu, d_ml, o);
                d_m  += __shfl_down_sync(0xffffffffu, d_m,  o);
            }
            if (lane == 0) {
                double smooth_loss = -d_sm / d_m;
                double ml_loss     = -d_ml / d_m;
                out[0] = (float)((double)ALPHA * smooth_loss
                                 + (1.0 - (double)ALPHA) * ml_loss);
                g_count = 0;   // reset for next graph replay
            }
        }
    }
}

// ---------------------------------------------------------------------------
extern "C" void kernel_launch(void* const* d_in, const int* in_sizes, int n_in,
                              void* d_out, int out_size)
{
    const float* logp       = (const float*)d_in[0];
    const float* mask       = (const float*)d_in[1];
    const float* sim_values = (const float*)d_in[2];
    const float* idf_values = (const float*)d_in[3];
    const int*   target     = (const int*)  d_in[4];
    const int*   sim_cols   = (const int*)  d_in[5];
    float*       out        = (float*)d_out;

    ws_fused_kernel<<<NROWS, TPB>>>(logp, mask, sim_values, idf_values,
                                    target, sim_cols, out);
}